// round 15
// baseline (speedup 1.0000x reference)
#include <cuda_runtime.h>
#include <cstdint>

#define BB 4
#define NN 1024
#define CC 1024
#define HH 16
#define HDIM 64

typedef unsigned long long ull;

// ---------------- scratch ----------------
static constexpr size_t OFF_Q    = 0;
static constexpr size_t OFF_K    = OFF_Q + (size_t)BB*HH*NN*HDIM;
static constexpr size_t OFF_VT   = OFF_K + (size_t)BB*HH*NN*HDIM;
static constexpr size_t OFF_MID  = OFF_VT + (size_t)BB*HH*NN*HDIM;   // mid[b][n][c]
static constexpr size_t OFF_PAV1 = OFF_MID + (size_t)BB*NN*CC;       // AV split-K partial 1
static constexpr size_t OFF_PP1  = OFF_PAV1 + (size_t)BB*NN*CC;      // proj split-K partial 1
static constexpr size_t OFF_S    = OFF_PP1 + (size_t)BB*NN*CC;
static constexpr size_t SCRATCH_TOTAL = OFF_S + (size_t)BB*HH*NN*NN;
__device__ float g_scratch[SCRATCH_TOTAL];

// ---------------- f32x2 helpers ----------------
__device__ __forceinline__ ull splat2(float v) {
  ull r; asm("mov.b64 %0, {%1,%1};" : "=l"(r) : "f"(v)); return r;
}
__device__ __forceinline__ ull pack2(float a, float b) {
  ull r; asm("mov.b64 %0, {%1,%2};" : "=l"(r) : "f"(a), "f"(b)); return r;
}
__device__ __forceinline__ void fma2(ull& d, ull a, ull b) {
  asm("fma.rn.f32x2 %0, %1, %2, %0;" : "+l"(d) : "l"(a), "l"(b));
}
__device__ __forceinline__ float lo32(ull u) { return __uint_as_float((unsigned)u); }
__device__ __forceinline__ float hi32(ull u) { return __uint_as_float((unsigned)(u >> 32)); }

// =========================================================================
// g5_gemm + split-K2 via ZB (UNCHANGED 1179us engine)
// =========================================================================
template <int EPI, int ZB>
__global__ __launch_bounds__(256, 3) void g5_gemm(
    const float* __restrict__ Ag, const float* __restrict__ Bg,
    int lda, int ldb, int K, size_t batchA, size_t batchB,
    const float* __restrict__ bias,
    float* __restrict__ O0, float* __restrict__ O1, float* __restrict__ O2,
    int ldo, size_t batchO) {
  constexpr int SRA = 132;   // 128 rows + pad
  constexpr int SRB = 68;    // 64 cols + pad
  __shared__ float As[2][16 * SRA];
  __shared__ float Bs[2][16 * SRB];

  const int tid = threadIdx.x;
  const int ty = tid >> 4, tx = tid & 15;  // 16 x 16
  const int r0 = ty * 8, c0 = tx * 4;
  const int rb = blockIdx.y * 128, ob = blockIdx.x * 64, z = blockIdx.z;
  const int sp = (ZB > 0) ? (z >= ZB ? 1 : 0) : 0;
  const int zz = (ZB > 0) ? (z - sp * ZB) : z;
  const int kbase = (ZB > 0) ? sp * (K >> 1) : 0;
  const int Keff = (ZB > 0) ? (K >> 1) : K;
  const float* Ab = Ag + (size_t)zz * batchA + kbase;
  const float* Bb = Bg + (size_t)zz * batchB + kbase;
  const int lr = tid >> 2, lk = (tid & 3) << 2;  // staging coords

  ull acc[4][4];
#pragma unroll
  for (int p = 0; p < 4; p++)
#pragma unroll
    for (int j = 0; j < 4; j++) acc[p][j] = 0ULL;

  float4 pa[2], pb;
  auto loadA = [&](int k0) {
#pragma unroll
    for (int i = 0; i < 2; i++)
      pa[i] = __ldg((const float4*)(Ab + (size_t)(rb + lr + i * 64) * lda + k0 + lk));
  };
  auto loadB = [&](int k0) {
    pb = __ldg((const float4*)(Bb + (size_t)(ob + lr) * ldb + k0 + lk));
  };
  auto stage = [&](int s) {
#pragma unroll
    for (int i = 0; i < 2; i++) {
      const int r = lr + i * 64;
      As[s][(lk + 0) * SRA + r] = pa[i].x; As[s][(lk + 1) * SRA + r] = pa[i].y;
      As[s][(lk + 2) * SRA + r] = pa[i].z; As[s][(lk + 3) * SRA + r] = pa[i].w;
    }
    Bs[s][(lk + 0) * SRB + lr] = pb.x; Bs[s][(lk + 1) * SRB + lr] = pb.y;
    Bs[s][(lk + 2) * SRB + lr] = pb.z; Bs[s][(lk + 3) * SRB + lr] = pb.w;
  };

  loadA(0); loadB(0);
  stage(0);
  __syncthreads();

  const int KT = Keff >> 4;
  int s = 0;
  for (int kt = 0; kt < KT; kt++) {
    if (kt + 1 < KT) { loadA((kt + 1) << 4); loadB((kt + 1) << 4); }
#pragma unroll
    for (int kk = 0; kk < 16; kk++) {
      float4 bf = *(const float4*)&Bs[s][kk * SRB + c0];
      ull sb[4] = {splat2(bf.x), splat2(bf.y), splat2(bf.z), splat2(bf.w)};
      const float* ar = &As[s][kk * SRA + r0];
      ulonglong2 u0 = *(const ulonglong2*)ar;
      ulonglong2 u1 = *(const ulonglong2*)(ar + 4);
      ull ap[4] = {u0.x, u0.y, u1.x, u1.y};
#pragma unroll
      for (int j = 0; j < 4; j++)
#pragma unroll
        for (int p = 0; p < 4; p++) fma2(acc[p][j], ap[p], sb[j]);
    }
    if (kt + 1 < KT) {
      stage(s ^ 1);
      __syncthreads();
    }
    s ^= 1;
  }

  float4 bi = make_float4(0.f, 0.f, 0.f, 0.f);
  if (EPI == 1) bi = __ldg((const float4*)(bias + ob + c0));
  const float bv[4] = {bi.x, bi.y, bi.z, bi.w};
#pragma unroll
  for (int p = 0; p < 4; p++) {
    const int r = rb + r0 + 2 * p;
    float lo[4], hi[4];
#pragma unroll
    for (int j = 0; j < 4; j++) { lo[j] = lo32(acc[p][j]); hi[j] = hi32(acc[p][j]); }
    if (EPI == 0) {
      float* dstB = (ZB > 0) ? (sp ? O1 : O0) + (size_t)zz * batchO
                             : O0 + (size_t)z * batchO;
      float* p0 = dstB + (size_t)r * ldo + ob + c0;
      *(float4*)p0 = make_float4(lo[0], lo[1], lo[2], lo[3]);
      *(float4*)(p0 + ldo) = make_float4(hi[0], hi[1], hi[2], hi[3]);
    } else if (EPI == 1) {
      const int cg = ob + c0;
      const int which = cg >> 10, h = (cg >> 6) & 15, d0 = cg & 63;
      const int b = r >> 10, n = r & 1023;
      if (which == 2) {
#pragma unroll
        for (int j = 0; j < 4; j++)
          *(float2*)(O2 + ((((size_t)b * HH + h) * HDIM + d0 + j) << 10) + n) =
              make_float2(lo[j] + bv[j], hi[j] + bv[j]);
      } else {
        float* dst = (which == 0) ? O0 : O1;
        const float sc = (which == 0) ? 0.125f : 1.0f;
        float* p0 = dst + (((size_t)b * HH + h) * NN + n) * HDIM + d0;
        *(float4*)p0 = make_float4((lo[0] + bv[0]) * sc, (lo[1] + bv[1]) * sc,
                                   (lo[2] + bv[2]) * sc, (lo[3] + bv[3]) * sc);
        *(float4*)(p0 + HDIM) = make_float4((hi[0] + bv[0]) * sc, (hi[1] + bv[1]) * sc,
                                            (hi[2] + bv[2]) * sc, (hi[3] + bv[3]) * sc);
      }
    } else {  // EPI == 2: AV partial -> (sp ? O1 : O0), mid layout
      const int b = zz >> 4, g = zz & 15;
      float* dstB = sp ? O1 : O0;
      float* p0 = dstB + (((size_t)b << 10) + r) * CC + (g << 6) + c0;
      *(float4*)p0 = make_float4(lo[0], lo[1], lo[2], lo[3]);
      *(float4*)(p0 + CC) = make_float4(hi[0], hi[1], hi[2], hi[3]);
    }
  }
}

// ---------------- split-K reduce kernels (unchanged) ----------------
__global__ __launch_bounds__(256) void red_av(float* __restrict__ mid,
                                              const float* __restrict__ p1) {
  const size_t i = ((size_t)blockIdx.x * 256 + threadIdx.x) * 4;
  float4 a = *(const float4*)(mid + i);
  float4 b = __ldg((const float4*)(p1 + i));
  *(float4*)(mid + i) = make_float4(a.x + b.x, a.y + b.y, a.z + b.z, a.w + b.w);
}
__global__ __launch_bounds__(256) void red_proj(float* __restrict__ out,
                                                const float* __restrict__ p1,
                                                const float* __restrict__ bias) {
  const size_t i = ((size_t)blockIdx.x * 256 + threadIdx.x) * 4;
  float4 a = *(const float4*)(out + i);
  float4 b = __ldg((const float4*)(p1 + i));
  float4 c = __ldg((const float4*)(bias + (i & 1023)));
  *(float4*)(out + i) = make_float4(a.x + b.x + c.x, a.y + b.y + c.y,
                                    a.z + b.z + c.z, a.w + b.w + c.w);
}

// =========================================================================
// fused mix1 + softmax + mix2 — smem-T, register-lean (two m-halves per
// phase so only [16] operand arrays are live; launch_bounds(256,3)).
// =========================================================================
__global__ __launch_bounds__(256, 3) void fused_mix_softmax(
    const float* __restrict__ wl, const float* __restrict__ bl,
    const float* __restrict__ ww, const float* __restrict__ bw,
    const float* __restrict__ s, float* __restrict__ attn) {
  extern __shared__ float sm[];
  float* T = sm;
  float* wls  = sm + 16 * 1024;
  float* wwi  = wls + 256;
  float* bls  = wwi + 256;
  float* bws  = bls + 16;
  float* invs = bws + 16;
  const int n = blockIdx.x, b = blockIdx.y, tid = threadIdx.x;
  const int lane = tid & 31;
  wls[tid] = wl[tid];
  if (tid < 16) bls[tid] = bl[tid];
  __syncthreads();

  // ---- phase 1: T[g][m] = sum_h wl[g,h]*s[b,h,n,m] + bl[g] (two halves) ----
  const float* sb = s + (((size_t)b * 16) << 20) + ((size_t)n << 10) + tid * 4;
#pragma unroll 1
  for (int half = 0; half < 2; half++) {
    ull sv[16];
#pragma unroll
    for (int h = 0; h < 16; h++) {
      float2 v = __ldg((const float2*)(sb + ((size_t)h << 20) + half * 2));
      sv[h] = pack2(v.x, v.y);
    }
#pragma unroll
    for (int g = 0; g < 16; g++) {
      ull a = splat2(bls[g]);
#pragma unroll
      for (int h = 0; h < 16; h++) fma2(a, splat2(wls[g * 16 + h]), sv[h]);
      *(float2*)&T[g * 1024 + tid * 4 + half * 2] = make_float2(lo32(a), hi32(a));
    }
  }
  __syncthreads();

  // ---- phase 2: softmax rows (warp w -> rows 2w, 2w+1) ----
  {
    const int g0 = (tid >> 5) * 2;
#pragma unroll
    for (int rr = 0; rr < 2; rr++) {
      float* row = &T[(g0 + rr) << 10];
      float v[32];
#pragma unroll
      for (int j = 0; j < 8; j++) {
        float4 x4 = *(const float4*)&row[lane * 4 + j * 128];
        v[j * 4 + 0] = x4.x; v[j * 4 + 1] = x4.y; v[j * 4 + 2] = x4.z; v[j * 4 + 3] = x4.w;
      }
      float mx = -1e30f;
#pragma unroll
      for (int i = 0; i < 32; i++) mx = fmaxf(mx, v[i]);
#pragma unroll
      for (int o = 16; o; o >>= 1) mx = fmaxf(mx, __shfl_xor_sync(0xffffffffu, mx, o));
      float sum = 0.f;
#pragma unroll
      for (int i = 0; i < 32; i++) { v[i] = __expf(v[i] - mx); sum += v[i]; }
#pragma unroll
      for (int o = 16; o; o >>= 1) sum += __shfl_xor_sync(0xffffffffu, sum, o);
#pragma unroll
      for (int j = 0; j < 8; j++)
        *(float4*)&row[lane * 4 + j * 128] =
            make_float4(v[j * 4 + 0], v[j * 4 + 1], v[j * 4 + 2], v[j * 4 + 3]);
      if (lane == 0) invs[g0 + rr] = 1.0f / sum;
    }
  }
  __syncthreads();
  wwi[tid] = ww[tid] * invs[tid & 15];
  if (tid < 16) bws[tid] = bw[tid];
  __syncthreads();

  // ---- phase 3: attn[g] = sum_h wwi[g,h]*exp[h] + bw[g] (two halves) ----
  float* ab = attn + (((size_t)b * 16) << 20) + ((size_t)n << 10) + tid * 4;
#pragma unroll 1
  for (int half = 0; half < 2; half++) {
    ull ev[16];
#pragma unroll
    for (int h = 0; h < 16; h++)
      ev[h] = *(const ull*)&T[h * 1024 + tid * 4 + half * 2];
#pragma unroll
    for (int g = 0; g < 16; g++) {
      ull a = splat2(bws[g]);
#pragma unroll
      for (int h = 0; h < 16; h++) fma2(a, splat2(wwi[g * 16 + h]), ev[h]);
      *(float2*)(ab + ((size_t)g << 20) + half * 2) = make_float2(lo32(a), hi32(a));
    }
  }
}

// ---------------- launch ----------------
extern "C" void kernel_launch(void* const* d_in, const int* in_sizes, int n_in,
                              void* d_out, int out_size) {
  const float* x      = (const float*)d_in[0];
  const float* qkv_w  = (const float*)d_in[1];
  const float* qkv_b  = (const float*)d_in[2];
  const float* proj_w = (const float*)d_in[3];
  const float* proj_b = (const float*)d_in[4];
  const float* wl     = (const float*)d_in[5];
  const float* bl     = (const float*)d_in[6];
  const float* ww     = (const float*)d_in[7];
  const float* bw     = (const float*)d_in[8];
  float* out = (float*)d_out;
  float* attn = out + (size_t)BB * NN * CC;

  float* scratch = nullptr;
  cudaGetSymbolAddress((void**)&scratch, g_scratch);
  float* q    = scratch + OFF_Q;
  float* k    = scratch + OFF_K;
  float* vT   = scratch + OFF_VT;
  float* mid  = scratch + OFF_MID;
  float* pav1 = scratch + OFF_PAV1;
  float* pp1  = scratch + OFF_PP1;
  float* s    = scratch + OFF_S;

  const int FUSED_SMEM = (16 * 1024 + 256 + 256 + 16 + 16 + 16) * 4;
  cudaFuncSetAttribute(fused_mix_softmax, cudaFuncAttributeMaxDynamicSharedMemorySize, FUSED_SMEM);

  // 1) qkv = x @ qkv_w^T + b -> q(*0.125), k, vT   (M=4096, N=3072, K=1024)
  g5_gemm<1, 0><<<dim3(48, 32, 1), 256>>>(
      x, qkv_w, CC, CC, CC, 0, 0, qkv_b, q, k, vT, 0, 0);
  // 2) s[b,h] = q[b,h] @ k[b,h]^T  (64 batches, M=N=1024, K=64)
  g5_gemm<0, 0><<<dim3(16, 8, 64), 256>>>(
      q, k, HDIM, HDIM, HDIM, (size_t)NN * HDIM, (size_t)NN * HDIM, nullptr,
      s, nullptr, nullptr, NN, (size_t)NN * NN);
  // 3) fused pre-mix + softmax + post-mix -> final attn
  fused_mix_softmax<<<dim3(NN, BB), 256, FUSED_SMEM>>>(wl, bl, ww, bw, s, attn);
  // 4) AV split-K2: halves -> mid / pav1  (64 batches x 2 K-halves)
  g5_gemm<2, 64><<<dim3(1, 8, 128), 256>>>(
      attn, vT, NN, NN, NN, (size_t)NN * NN, (size_t)HDIM * NN, nullptr,
      mid, pav1, nullptr, 0, 0);
  //    reduce: mid += pav1
  red_av<<<(BB * NN * CC) / (256 * 4), 256>>>(mid, pav1);
  // 5) proj split-K2: halves -> out / pp1  (M=4096, N=1024)
  g5_gemm<0, 1><<<dim3(16, 32, 2), 256>>>(
      mid, proj_w, CC, CC, CC, 0, 0, nullptr, out, pp1, nullptr, CC, 0);
  //    reduce: out += pp1 + bias
  red_proj<<<(BB * NN * CC) / (256 * 4), 256>>>(out, pp1, proj_b);
}

// round 16
// speedup vs baseline: 1.3366x; 1.3366x over previous
#include <cuda_runtime.h>
#include <cstdint>

#define BB 4
#define NN 1024
#define CC 1024
#define HH 16
#define HDIM 64

typedef unsigned long long ull;

// ---------------- scratch ----------------
static constexpr size_t OFF_Q    = 0;
static constexpr size_t OFF_K    = OFF_Q + (size_t)BB*HH*NN*HDIM;
static constexpr size_t OFF_VT   = OFF_K + (size_t)BB*HH*NN*HDIM;
static constexpr size_t OFF_MID  = OFF_VT + (size_t)BB*HH*NN*HDIM;   // mid[b][n][c] (AV half 0)
static constexpr size_t OFF_PAV1 = OFF_MID + (size_t)BB*NN*CC;       // AV split-K partial 1
static constexpr size_t OFF_PP1  = OFF_PAV1 + (size_t)BB*NN*CC;      // proj split-K partial 1
static constexpr size_t OFF_S    = OFF_PP1 + (size_t)BB*NN*CC;
static constexpr size_t SCRATCH_TOTAL = OFF_S + (size_t)BB*HH*NN*NN;
__device__ float g_scratch[SCRATCH_TOTAL];

// ---------------- f32x2 helpers ----------------
__device__ __forceinline__ ull splat2(float v) {
  ull r; asm("mov.b64 %0, {%1,%1};" : "=l"(r) : "f"(v)); return r;
}
__device__ __forceinline__ void fma2(ull& d, ull a, ull b) {
  asm("fma.rn.f32x2 %0, %1, %2, %0;" : "+l"(d) : "l"(a), "l"(b));
}
__device__ __forceinline__ float lo32(ull u) { return __uint_as_float((unsigned)u); }
__device__ __forceinline__ float hi32(ull u) { return __uint_as_float((unsigned)(u >> 32)); }

// =========================================================================
// g5_gemm + split-K2 via ZB + optional ASUM (A = Ag + Ag2 elementwise).
//   ZB == 0 : normal, z = batch index, full K.
//   ZB  > 0 : grid.z = 2*ZB; sp = z/ZB K-half; zz = z%ZB batch; dst sp?O1:O0.
// EPI: 0 plain (split-aware), 1 qkv scatter, 2 AV->mid (split-aware)
// =========================================================================
template <int EPI, int ZB, int ASUM>
__global__ __launch_bounds__(256, 3) void g5_gemm(
    const float* __restrict__ Ag, const float* __restrict__ Ag2,
    const float* __restrict__ Bg,
    int lda, int ldb, int K, size_t batchA, size_t batchB,
    const float* __restrict__ bias,
    float* __restrict__ O0, float* __restrict__ O1, float* __restrict__ O2,
    int ldo, size_t batchO) {
  constexpr int SRA = 132;   // 128 rows + pad
  constexpr int SRB = 68;    // 64 cols + pad
  __shared__ float As[2][16 * SRA];
  __shared__ float Bs[2][16 * SRB];

  const int tid = threadIdx.x;
  const int ty = tid >> 4, tx = tid & 15;  // 16 x 16
  const int r0 = ty * 8, c0 = tx * 4;
  const int rb = blockIdx.y * 128, ob = blockIdx.x * 64, z = blockIdx.z;
  const int sp = (ZB > 0) ? (z >= ZB ? 1 : 0) : 0;
  const int zz = (ZB > 0) ? (z - sp * ZB) : z;
  const int kbase = (ZB > 0) ? sp * (K >> 1) : 0;
  const int Keff = (ZB > 0) ? (K >> 1) : K;
  const float* Ab = Ag + (size_t)zz * batchA + kbase;
  const float* Ab2 = ASUM ? (Ag2 + (size_t)zz * batchA + kbase) : nullptr;
  const float* Bb = Bg + (size_t)zz * batchB + kbase;
  const int lr = tid >> 2, lk = (tid & 3) << 2;  // staging coords

  ull acc[4][4];
#pragma unroll
  for (int p = 0; p < 4; p++)
#pragma unroll
    for (int j = 0; j < 4; j++) acc[p][j] = 0ULL;

  float4 pa[2], pb;
  auto loadA = [&](int k0) {
#pragma unroll
    for (int i = 0; i < 2; i++) {
      const size_t off = (size_t)(rb + lr + i * 64) * lda + k0 + lk;
      pa[i] = __ldg((const float4*)(Ab + off));
      if (ASUM) {
        float4 t = __ldg((const float4*)(Ab2 + off));
        pa[i].x += t.x; pa[i].y += t.y; pa[i].z += t.z; pa[i].w += t.w;
      }
    }
  };
  auto loadB = [&](int k0) {
    pb = __ldg((const float4*)(Bb + (size_t)(ob + lr) * ldb + k0 + lk));
  };
  auto stage = [&](int s) {
#pragma unroll
    for (int i = 0; i < 2; i++) {
      const int r = lr + i * 64;
      As[s][(lk + 0) * SRA + r] = pa[i].x; As[s][(lk + 1) * SRA + r] = pa[i].y;
      As[s][(lk + 2) * SRA + r] = pa[i].z; As[s][(lk + 3) * SRA + r] = pa[i].w;
    }
    Bs[s][(lk + 0) * SRB + lr] = pb.x; Bs[s][(lk + 1) * SRB + lr] = pb.y;
    Bs[s][(lk + 2) * SRB + lr] = pb.z; Bs[s][(lk + 3) * SRB + lr] = pb.w;
  };

  loadA(0); loadB(0);
  stage(0);
  __syncthreads();

  const int KT = Keff >> 4;
  int s = 0;
  for (int kt = 0; kt < KT; kt++) {
    if (kt + 1 < KT) { loadA((kt + 1) << 4); loadB((kt + 1) << 4); }
#pragma unroll
    for (int kk = 0; kk < 16; kk++) {
      float4 bf = *(const float4*)&Bs[s][kk * SRB + c0];
      ull sb[4] = {splat2(bf.x), splat2(bf.y), splat2(bf.z), splat2(bf.w)};
      const float* ar = &As[s][kk * SRA + r0];
      ulonglong2 u0 = *(const ulonglong2*)ar;
      ulonglong2 u1 = *(const ulonglong2*)(ar + 4);
      ull ap[4] = {u0.x, u0.y, u1.x, u1.y};
#pragma unroll
      for (int j = 0; j < 4; j++)
#pragma unroll
        for (int p = 0; p < 4; p++) fma2(acc[p][j], ap[p], sb[j]);
    }
    if (kt + 1 < KT) {
      stage(s ^ 1);
      __syncthreads();
    }
    s ^= 1;
  }

  float4 bi = make_float4(0.f, 0.f, 0.f, 0.f);
  if (EPI == 1) bi = __ldg((const float4*)(bias + ob + c0));
  const float bv[4] = {bi.x, bi.y, bi.z, bi.w};
#pragma unroll
  for (int p = 0; p < 4; p++) {
    const int r = rb + r0 + 2 * p;
    float lo[4], hi[4];
#pragma unroll
    for (int j = 0; j < 4; j++) { lo[j] = lo32(acc[p][j]); hi[j] = hi32(acc[p][j]); }
    if (EPI == 0) {
      float* dstB = (ZB > 0) ? (sp ? O1 : O0) + (size_t)zz * batchO
                             : O0 + (size_t)z * batchO;
      float* p0 = dstB + (size_t)r * ldo + ob + c0;
      *(float4*)p0 = make_float4(lo[0], lo[1], lo[2], lo[3]);
      *(float4*)(p0 + ldo) = make_float4(hi[0], hi[1], hi[2], hi[3]);
    } else if (EPI == 1) {
      const int cg = ob + c0;
      const int which = cg >> 10, h = (cg >> 6) & 15, d0 = cg & 63;
      const int b = r >> 10, n = r & 1023;
      if (which == 2) {
#pragma unroll
        for (int j = 0; j < 4; j++)
          *(float2*)(O2 + ((((size_t)b * HH + h) * HDIM + d0 + j) << 10) + n) =
              make_float2(lo[j] + bv[j], hi[j] + bv[j]);
      } else {
        float* dst = (which == 0) ? O0 : O1;
        const float sc = (which == 0) ? 0.125f : 1.0f;
        float* p0 = dst + (((size_t)b * HH + h) * NN + n) * HDIM + d0;
        *(float4*)p0 = make_float4((lo[0] + bv[0]) * sc, (lo[1] + bv[1]) * sc,
                                   (lo[2] + bv[2]) * sc, (lo[3] + bv[3]) * sc);
        *(float4*)(p0 + HDIM) = make_float4((hi[0] + bv[0]) * sc, (hi[1] + bv[1]) * sc,
                                            (hi[2] + bv[2]) * sc, (hi[3] + bv[3]) * sc);
      }
    } else {  // EPI == 2: AV partial -> (sp ? O1 : O0), mid layout
      const int b = zz >> 4, g = zz & 15;
      float* dstB = sp ? O1 : O0;
      float* p0 = dstB + (((size_t)b << 10) + r) * CC + (g << 6) + c0;
      *(float4*)p0 = make_float4(lo[0], lo[1], lo[2], lo[3]);
      *(float4*)(p0 + CC) = make_float4(hi[0], hi[1], hi[2], hi[3]);
    }
  }
}

// ---------------- proj final reduce: out += pp1 + bias ----------------
__global__ __launch_bounds__(256) void red_proj(float* __restrict__ out,
                                                const float* __restrict__ p1,
                                                const float* __restrict__ bias) {
  const size_t i = ((size_t)blockIdx.x * 256 + threadIdx.x) * 4;
  float4 a = *(const float4*)(out + i);
  float4 b = __ldg((const float4*)(p1 + i));
  float4 c = __ldg((const float4*)(bias + (i & 1023)));
  *(float4*)(out + i) = make_float4(a.x + b.x + c.x, a.y + b.y + c.y,
                                    a.z + b.z + c.z, a.w + b.w + c.w);
}

// =========================================================================
// fused mix1 + softmax + mix2 (FMA2, smem-T) — EXACT R12 version (1179us)
// =========================================================================
__global__ __launch_bounds__(256) void fused_mix_softmax(
    const float* __restrict__ wl, const float* __restrict__ bl,
    const float* __restrict__ ww, const float* __restrict__ bw,
    const float* __restrict__ s, float* __restrict__ attn) {
  extern __shared__ float sm[];
  float* T = sm;
  float* wls  = sm + 16 * 1024;
  float* wwi  = wls + 256;
  float* bls  = wwi + 256;
  float* bws  = bls + 16;
  float* invs = bws + 16;
  const int n = blockIdx.x, b = blockIdx.y, tid = threadIdx.x;
  const int lane = tid & 31;
  wls[tid] = wl[tid];
  if (tid < 16) bls[tid] = bl[tid];
  __syncthreads();

  const float* sb = s + (((size_t)b * 16) << 20) + ((size_t)n << 10) + tid * 4;
  {
    ull sv[16][2];
#pragma unroll
    for (int h = 0; h < 16; h++) {
      float4 v = __ldg((const float4*)(sb + ((size_t)h << 20)));
      asm("mov.b64 %0, {%1,%2};" : "=l"(sv[h][0]) : "f"(v.x), "f"(v.y));
      asm("mov.b64 %0, {%1,%2};" : "=l"(sv[h][1]) : "f"(v.z), "f"(v.w));
    }
#pragma unroll
    for (int g = 0; g < 16; g++) {
      ull a0 = splat2(bls[g]), a1 = a0;
#pragma unroll
      for (int h = 0; h < 16; h++) {
        ull wsp = splat2(wls[g * 16 + h]);
        fma2(a0, wsp, sv[h][0]);
        fma2(a1, wsp, sv[h][1]);
      }
      *(float4*)&T[g * 1024 + tid * 4] = make_float4(lo32(a0), hi32(a0), lo32(a1), hi32(a1));
    }
  }
  __syncthreads();

  {
    const int g0 = (tid >> 5) * 2;
#pragma unroll
    for (int rr = 0; rr < 2; rr++) {
      float* row = &T[(g0 + rr) << 10];
      float v[32];
#pragma unroll
      for (int j = 0; j < 8; j++) {
        float4 x4 = *(const float4*)&row[lane * 4 + j * 128];
        v[j * 4 + 0] = x4.x; v[j * 4 + 1] = x4.y; v[j * 4 + 2] = x4.z; v[j * 4 + 3] = x4.w;
      }
      float mx = -1e30f;
#pragma unroll
      for (int i = 0; i < 32; i++) mx = fmaxf(mx, v[i]);
#pragma unroll
      for (int o = 16; o; o >>= 1) mx = fmaxf(mx, __shfl_xor_sync(0xffffffffu, mx, o));
      float sum = 0.f;
#pragma unroll
      for (int i = 0; i < 32; i++) { v[i] = __expf(v[i] - mx); sum += v[i]; }
#pragma unroll
      for (int o = 16; o; o >>= 1) sum += __shfl_xor_sync(0xffffffffu, sum, o);
#pragma unroll
      for (int j = 0; j < 8; j++)
        *(float4*)&row[lane * 4 + j * 128] =
            make_float4(v[j * 4 + 0], v[j * 4 + 1], v[j * 4 + 2], v[j * 4 + 3]);
      if (lane == 0) invs[g0 + rr] = 1.0f / sum;
    }
  }
  __syncthreads();
  wwi[tid] = ww[tid] * invs[tid & 15];
  if (tid < 16) bws[tid] = bw[tid];
  __syncthreads();

  float* ab = attn + (((size_t)b * 16) << 20) + ((size_t)n << 10) + tid * 4;
  {
    ull ev[16][2];
#pragma unroll
    for (int h = 0; h < 16; h++) {
      ulonglong2 u = *(const ulonglong2*)&T[h * 1024 + tid * 4];
      ev[h][0] = u.x; ev[h][1] = u.y;
    }
#pragma unroll
    for (int g = 0; g < 16; g++) {
      ull a0 = splat2(bws[g]), a1 = a0;
#pragma unroll
      for (int h = 0; h < 16; h++) {
        ull wsp = splat2(wwi[g * 16 + h]);
        fma2(a0, wsp, ev[h][0]);
        fma2(a1, wsp, ev[h][1]);
      }
      *(float4*)(ab + ((size_t)g << 20)) = make_float4(lo32(a0), hi32(a0), lo32(a1), hi32(a1));
    }
  }
}

// ---------------- launch ----------------
extern "C" void kernel_launch(void* const* d_in, const int* in_sizes, int n_in,
                              void* d_out, int out_size) {
  const float* x      = (const float*)d_in[0];
  const float* qkv_w  = (const float*)d_in[1];
  const float* qkv_b  = (const float*)d_in[2];
  const float* proj_w = (const float*)d_in[3];
  const float* proj_b = (const float*)d_in[4];
  const float* wl     = (const float*)d_in[5];
  const float* bl     = (const float*)d_in[6];
  const float* ww     = (const float*)d_in[7];
  const float* bw     = (const float*)d_in[8];
  float* out = (float*)d_out;
  float* attn = out + (size_t)BB * NN * CC;

  float* scratch = nullptr;
  cudaGetSymbolAddress((void**)&scratch, g_scratch);
  float* q    = scratch + OFF_Q;
  float* k    = scratch + OFF_K;
  float* vT   = scratch + OFF_VT;
  float* mid  = scratch + OFF_MID;
  float* pav1 = scratch + OFF_PAV1;
  float* pp1  = scratch + OFF_PP1;
  float* s    = scratch + OFF_S;

  const int FUSED_SMEM = (16 * 1024 + 256 + 256 + 16 + 16 + 16) * 4;
  cudaFuncSetAttribute(fused_mix_softmax, cudaFuncAttributeMaxDynamicSharedMemorySize, FUSED_SMEM);

  // 1) qkv = x @ qkv_w^T + b -> q(*0.125), k, vT   (M=4096, N=3072, K=1024)
  g5_gemm<1, 0, 0><<<dim3(48, 32, 1), 256>>>(
      x, nullptr, qkv_w, CC, CC, CC, 0, 0, qkv_b, q, k, vT, 0, 0);
  // 2) s[b,h] = q[b,h] @ k[b,h]^T  (64 batches, M=N=1024, K=64)
  g5_gemm<0, 0, 0><<<dim3(16, 8, 64), 256>>>(
      q, nullptr, k, HDIM, HDIM, HDIM, (size_t)NN * HDIM, (size_t)NN * HDIM, nullptr,
      s, nullptr, nullptr, NN, (size_t)NN * NN);
  // 3) fused pre-mix + softmax + post-mix -> final attn
  fused_mix_softmax<<<dim3(NN, BB), 256, FUSED_SMEM>>>(wl, bl, ww, bw, s, attn);
  // 4) AV split-K2: halves -> mid / pav1  (64 batches x 2 K-halves)
  g5_gemm<2, 64, 0><<<dim3(1, 8, 128), 256>>>(
      attn, nullptr, vT, NN, NN, NN, (size_t)NN * NN, (size_t)HDIM * NN, nullptr,
      mid, pav1, nullptr, 0, 0);
  // 5) proj split-K2 with fused AV-reduce: A = mid + pav1 on load
  g5_gemm<0, 1, 1><<<dim3(16, 32, 2), 256>>>(
      mid, pav1, proj_w, CC, CC, CC, 0, 0, nullptr, out, pp1, nullptr, CC, 0);
  //    reduce: out += pp1 + bias
  red_proj<<<(BB * NN * CC) / (256 * 4), 256>>>(out, pp1, proj_b);
}

// round 17
// speedup vs baseline: 1.3930x; 1.0422x over previous
#include <cuda_runtime.h>
#include <cuda_bf16.h>
#include <cstdint>

#define BB 4
#define NN 1024
#define CC 1024
#define HH 16
#define HDIM 64

typedef unsigned long long ull;

// ---------------- scratch ----------------
static constexpr size_t OFF_Q    = 0;
static constexpr size_t OFF_K    = OFF_Q + (size_t)BB*HH*NN*HDIM;
static constexpr size_t OFF_VT   = OFF_K + (size_t)BB*HH*NN*HDIM;
static constexpr size_t OFF_MID  = OFF_VT + (size_t)BB*HH*NN*HDIM;   // mid[b][n][c]
static constexpr size_t OFF_PAV1 = OFF_MID + (size_t)BB*NN*CC;       // AV split-K partial 1
static constexpr size_t OFF_PP1  = OFF_PAV1 + (size_t)BB*NN*CC;      // proj split-K partial 1
static constexpr size_t OFF_S    = OFF_PP1 + (size_t)BB*NN*CC;       // s as bf16 (uses half)
static constexpr size_t SCRATCH_TOTAL = OFF_S + (size_t)BB*HH*NN*NN; // generous
__device__ float g_scratch[SCRATCH_TOTAL];

// ---------------- f32x2 helpers ----------------
__device__ __forceinline__ ull splat2(float v) {
  ull r; asm("mov.b64 %0, {%1,%1};" : "=l"(r) : "f"(v)); return r;
}
__device__ __forceinline__ ull pack2(float a, float b) {
  ull r; asm("mov.b64 %0, {%1,%2};" : "=l"(r) : "f"(a), "f"(b)); return r;
}
__device__ __forceinline__ void fma2(ull& d, ull a, ull b) {
  asm("fma.rn.f32x2 %0, %1, %2, %0;" : "+l"(d) : "l"(a), "l"(b));
}
__device__ __forceinline__ float lo32(ull u) { return __uint_as_float((unsigned)u); }
__device__ __forceinline__ float hi32(ull u) { return __uint_as_float((unsigned)(u >> 32)); }

// =========================================================================
// g5_gemm + split-K2 via ZB (1179us engine).
// EPI: 0 plain fp32 (split-aware), 1 qkv scatter, 2 AV->mid (split-aware),
//      4 plain bf16 store (for QK logits)
// =========================================================================
template <int EPI, int ZB>
__global__ __launch_bounds__(256, 3) void g5_gemm(
    const float* __restrict__ Ag, const float* __restrict__ Bg,
    int lda, int ldb, int K, size_t batchA, size_t batchB,
    const float* __restrict__ bias,
    float* __restrict__ O0, float* __restrict__ O1, float* __restrict__ O2,
    int ldo, size_t batchO) {
  constexpr int SRA = 132;   // 128 rows + pad
  constexpr int SRB = 68;    // 64 cols + pad
  __shared__ float As[2][16 * SRA];
  __shared__ float Bs[2][16 * SRB];

  const int tid = threadIdx.x;
  const int ty = tid >> 4, tx = tid & 15;  // 16 x 16
  const int r0 = ty * 8, c0 = tx * 4;
  const int rb = blockIdx.y * 128, ob = blockIdx.x * 64, z = blockIdx.z;
  const int sp = (ZB > 0) ? (z >= ZB ? 1 : 0) : 0;
  const int zz = (ZB > 0) ? (z - sp * ZB) : z;
  const int kbase = (ZB > 0) ? sp * (K >> 1) : 0;
  const int Keff = (ZB > 0) ? (K >> 1) : K;
  const float* Ab = Ag + (size_t)zz * batchA + kbase;
  const float* Bb = Bg + (size_t)zz * batchB + kbase;
  const int lr = tid >> 2, lk = (tid & 3) << 2;  // staging coords

  ull acc[4][4];
#pragma unroll
  for (int p = 0; p < 4; p++)
#pragma unroll
    for (int j = 0; j < 4; j++) acc[p][j] = 0ULL;

  float4 pa[2], pb;
  auto loadA = [&](int k0) {
#pragma unroll
    for (int i = 0; i < 2; i++)
      pa[i] = __ldg((const float4*)(Ab + (size_t)(rb + lr + i * 64) * lda + k0 + lk));
  };
  auto loadB = [&](int k0) {
    pb = __ldg((const float4*)(Bb + (size_t)(ob + lr) * ldb + k0 + lk));
  };
  auto stage = [&](int s) {
#pragma unroll
    for (int i = 0; i < 2; i++) {
      const int r = lr + i * 64;
      As[s][(lk + 0) * SRA + r] = pa[i].x; As[s][(lk + 1) * SRA + r] = pa[i].y;
      As[s][(lk + 2) * SRA + r] = pa[i].z; As[s][(lk + 3) * SRA + r] = pa[i].w;
    }
    Bs[s][(lk + 0) * SRB + lr] = pb.x; Bs[s][(lk + 1) * SRB + lr] = pb.y;
    Bs[s][(lk + 2) * SRB + lr] = pb.z; Bs[s][(lk + 3) * SRB + lr] = pb.w;
  };

  loadA(0); loadB(0);
  stage(0);
  __syncthreads();

  const int KT = Keff >> 4;
  int s = 0;
  for (int kt = 0; kt < KT; kt++) {
    if (kt + 1 < KT) { loadA((kt + 1) << 4); loadB((kt + 1) << 4); }
#pragma unroll
    for (int kk = 0; kk < 16; kk++) {
      float4 bf = *(const float4*)&Bs[s][kk * SRB + c0];
      ull sb[4] = {splat2(bf.x), splat2(bf.y), splat2(bf.z), splat2(bf.w)};
      const float* ar = &As[s][kk * SRA + r0];
      ulonglong2 u0 = *(const ulonglong2*)ar;
      ulonglong2 u1 = *(const ulonglong2*)(ar + 4);
      ull ap[4] = {u0.x, u0.y, u1.x, u1.y};
#pragma unroll
      for (int j = 0; j < 4; j++)
#pragma unroll
        for (int p = 0; p < 4; p++) fma2(acc[p][j], ap[p], sb[j]);
    }
    if (kt + 1 < KT) {
      stage(s ^ 1);
      __syncthreads();
    }
    s ^= 1;
  }

  float4 bi = make_float4(0.f, 0.f, 0.f, 0.f);
  if (EPI == 1) bi = __ldg((const float4*)(bias + ob + c0));
  const float bv[4] = {bi.x, bi.y, bi.z, bi.w};
#pragma unroll
  for (int p = 0; p < 4; p++) {
    const int r = rb + r0 + 2 * p;
    float lo[4], hi[4];
#pragma unroll
    for (int j = 0; j < 4; j++) { lo[j] = lo32(acc[p][j]); hi[j] = hi32(acc[p][j]); }
    if (EPI == 0) {
      float* dstB = (ZB > 0) ? (sp ? O1 : O0) + (size_t)zz * batchO
                             : O0 + (size_t)z * batchO;
      float* p0 = dstB + (size_t)r * ldo + ob + c0;
      *(float4*)p0 = make_float4(lo[0], lo[1], lo[2], lo[3]);
      *(float4*)(p0 + ldo) = make_float4(hi[0], hi[1], hi[2], hi[3]);
    } else if (EPI == 4) {
      // bf16 plain store (QK logits): 4 cols -> 8 bytes per row
      __nv_bfloat16* dstB = (__nv_bfloat16*)O0 + (size_t)z * batchO;
      __nv_bfloat16* p0 = dstB + (size_t)r * ldo + ob + c0;
      __nv_bfloat162 l01 = __float22bfloat162_rn(make_float2(lo[0], lo[1]));
      __nv_bfloat162 l23 = __float22bfloat162_rn(make_float2(lo[2], lo[3]));
      *(uint2*)p0 = make_uint2(*(unsigned*)&l01, *(unsigned*)&l23);
      __nv_bfloat162 h01 = __float22bfloat162_rn(make_float2(hi[0], hi[1]));
      __nv_bfloat162 h23 = __float22bfloat162_rn(make_float2(hi[2], hi[3]));
      *(uint2*)(p0 + ldo) = make_uint2(*(unsigned*)&h01, *(unsigned*)&h23);
    } else if (EPI == 1) {
      const int cg = ob + c0;
      const int which = cg >> 10, h = (cg >> 6) & 15, d0 = cg & 63;
      const int b = r >> 10, n = r & 1023;
      if (which == 2) {
#pragma unroll
        for (int j = 0; j < 4; j++)
          *(float2*)(O2 + ((((size_t)b * HH + h) * HDIM + d0 + j) << 10) + n) =
              make_float2(lo[j] + bv[j], hi[j] + bv[j]);
      } else {
        float* dst = (which == 0) ? O0 : O1;
        const float sc = (which == 0) ? 0.125f : 1.0f;
        float* p0 = dst + (((size_t)b * HH + h) * NN + n) * HDIM + d0;
        *(float4*)p0 = make_float4((lo[0] + bv[0]) * sc, (lo[1] + bv[1]) * sc,
                                   (lo[2] + bv[2]) * sc, (lo[3] + bv[3]) * sc);
        *(float4*)(p0 + HDIM) = make_float4((hi[0] + bv[0]) * sc, (hi[1] + bv[1]) * sc,
                                            (hi[2] + bv[2]) * sc, (hi[3] + bv[3]) * sc);
      }
    } else {  // EPI == 2: AV partial -> (sp ? O1 : O0), mid layout
      const int b = zz >> 4, g = zz & 15;
      float* dstB = sp ? O1 : O0;
      float* p0 = dstB + (((size_t)b << 10) + r) * CC + (g << 6) + c0;
      *(float4*)p0 = make_float4(lo[0], lo[1], lo[2], lo[3]);
      *(float4*)(p0 + CC) = make_float4(hi[0], hi[1], hi[2], hi[3]);
    }
  }
}

// ---------------- split-K reduce kernels (R12) ----------------
__global__ __launch_bounds__(256) void red_av(float* __restrict__ mid,
                                              const float* __restrict__ p1) {
  const size_t i = ((size_t)blockIdx.x * 256 + threadIdx.x) * 4;
  float4 a = *(const float4*)(mid + i);
  float4 b = __ldg((const float4*)(p1 + i));
  *(float4*)(mid + i) = make_float4(a.x + b.x, a.y + b.y, a.z + b.z, a.w + b.w);
}
__global__ __launch_bounds__(256) void red_proj(float* __restrict__ out,
                                                const float* __restrict__ p1,
                                                const float* __restrict__ bias) {
  const size_t i = ((size_t)blockIdx.x * 256 + threadIdx.x) * 4;
  float4 a = *(const float4*)(out + i);
  float4 b = __ldg((const float4*)(p1 + i));
  float4 c = __ldg((const float4*)(bias + (i & 1023)));
  *(float4*)(out + i) = make_float4(a.x + b.x + c.x, a.y + b.y + c.y,
                                    a.z + b.z + c.z, a.w + b.w + c.w);
}

// =========================================================================
// fused mix1 + softmax + mix2 — R12 structure; phase 1 reads bf16 s.
// =========================================================================
__global__ __launch_bounds__(256) void fused_mix_softmax(
    const float* __restrict__ wl, const float* __restrict__ bl,
    const float* __restrict__ ww, const float* __restrict__ bw,
    const __nv_bfloat16* __restrict__ s, float* __restrict__ attn) {
  extern __shared__ float sm[];
  float* T = sm;
  float* wls  = sm + 16 * 1024;
  float* wwi  = wls + 256;
  float* bls  = wwi + 256;
  float* bws  = bls + 16;
  float* invs = bws + 16;
  const int n = blockIdx.x, b = blockIdx.y, tid = threadIdx.x;
  const int lane = tid & 31;
  wls[tid] = wl[tid];
  if (tid < 16) bls[tid] = bl[tid];
  __syncthreads();

  const __nv_bfloat16* sb = s + (((size_t)b * 16) << 20) + ((size_t)n << 10) + tid * 4;
  {
    ull sv[16][2];
#pragma unroll
    for (int h = 0; h < 16; h++) {
      uint2 raw = __ldg((const uint2*)(sb + ((size_t)h << 20)));
      __nv_bfloat162 x01 = *(__nv_bfloat162*)&raw.x;
      __nv_bfloat162 x23 = *(__nv_bfloat162*)&raw.y;
      float2 f01 = __bfloat1622float2(x01);
      float2 f23 = __bfloat1622float2(x23);
      sv[h][0] = pack2(f01.x, f01.y);
      sv[h][1] = pack2(f23.x, f23.y);
    }
#pragma unroll
    for (int g = 0; g < 16; g++) {
      ull a0 = splat2(bls[g]), a1 = a0;
#pragma unroll
      for (int h = 0; h < 16; h++) {
        ull wsp = splat2(wls[g * 16 + h]);
        fma2(a0, wsp, sv[h][0]);
        fma2(a1, wsp, sv[h][1]);
      }
      *(float4*)&T[g * 1024 + tid * 4] = make_float4(lo32(a0), hi32(a0), lo32(a1), hi32(a1));
    }
  }
  __syncthreads();

  {
    const int g0 = (tid >> 5) * 2;
#pragma unroll
    for (int rr = 0; rr < 2; rr++) {
      float* row = &T[(g0 + rr) << 10];
      float v[32];
#pragma unroll
      for (int j = 0; j < 8; j++) {
        float4 x4 = *(const float4*)&row[lane * 4 + j * 128];
        v[j * 4 + 0] = x4.x; v[j * 4 + 1] = x4.y; v[j * 4 + 2] = x4.z; v[j * 4 + 3] = x4.w;
      }
      float mx = -1e30f;
#pragma unroll
      for (int i = 0; i < 32; i++) mx = fmaxf(mx, v[i]);
#pragma unroll
      for (int o = 16; o; o >>= 1) mx = fmaxf(mx, __shfl_xor_sync(0xffffffffu, mx, o));
      float sum = 0.f;
#pragma unroll
      for (int i = 0; i < 32; i++) { v[i] = __expf(v[i] - mx); sum += v[i]; }
#pragma unroll
      for (int o = 16; o; o >>= 1) sum += __shfl_xor_sync(0xffffffffu, sum, o);
#pragma unroll
      for (int j = 0; j < 8; j++)
        *(float4*)&row[lane * 4 + j * 128] =
            make_float4(v[j * 4 + 0], v[j * 4 + 1], v[j * 4 + 2], v[j * 4 + 3]);
      if (lane == 0) invs[g0 + rr] = 1.0f / sum;
    }
  }
  __syncthreads();
  wwi[tid] = ww[tid] * invs[tid & 15];
  if (tid < 16) bws[tid] = bw[tid];
  __syncthreads();

  float* ab = attn + (((size_t)b * 16) << 20) + ((size_t)n << 10) + tid * 4;
  {
    ull ev[16][2];
#pragma unroll
    for (int h = 0; h < 16; h++) {
      ulonglong2 u = *(const ulonglong2*)&T[h * 1024 + tid * 4];
      ev[h][0] = u.x; ev[h][1] = u.y;
    }
#pragma unroll
    for (int g = 0; g < 16; g++) {
      ull a0 = splat2(bws[g]), a1 = a0;
#pragma unroll
      for (int h = 0; h < 16; h++) {
        ull wsp = splat2(wwi[g * 16 + h]);
        fma2(a0, wsp, ev[h][0]);
        fma2(a1, wsp, ev[h][1]);
      }
      *(float4*)(ab + ((size_t)g << 20)) = make_float4(lo32(a0), hi32(a0), lo32(a1), hi32(a1));
    }
  }
}

// ---------------- launch ----------------
extern "C" void kernel_launch(void* const* d_in, const int* in_sizes, int n_in,
                              void* d_out, int out_size) {
  const float* x      = (const float*)d_in[0];
  const float* qkv_w  = (const float*)d_in[1];
  const float* qkv_b  = (const float*)d_in[2];
  const float* proj_w = (const float*)d_in[3];
  const float* proj_b = (const float*)d_in[4];
  const float* wl     = (const float*)d_in[5];
  const float* bl     = (const float*)d_in[6];
  const float* ww     = (const float*)d_in[7];
  const float* bw     = (const float*)d_in[8];
  float* out = (float*)d_out;
  float* attn = out + (size_t)BB * NN * CC;

  float* scratch = nullptr;
  cudaGetSymbolAddress((void**)&scratch, g_scratch);
  float* q    = scratch + OFF_Q;
  float* k    = scratch + OFF_K;
  float* vT   = scratch + OFF_VT;
  float* mid  = scratch + OFF_MID;
  float* pav1 = scratch + OFF_PAV1;
  float* pp1  = scratch + OFF_PP1;
  float* s_f  = scratch + OFF_S;           // used as bf16 buffer
  __nv_bfloat16* s_bf = (__nv_bfloat16*)s_f;

  const int FUSED_SMEM = (16 * 1024 + 256 + 256 + 16 + 16 + 16) * 4;
  cudaFuncSetAttribute(fused_mix_softmax, cudaFuncAttributeMaxDynamicSharedMemorySize, FUSED_SMEM);

  // 1) qkv = x @ qkv_w^T + b -> q(*0.125), k, vT   (M=4096, N=3072, K=1024)
  g5_gemm<1, 0><<<dim3(48, 32, 1), 256>>>(
      x, qkv_w, CC, CC, CC, 0, 0, qkv_b, q, k, vT, 0, 0);
  // 2) s[b,h] = q[b,h] @ k[b,h]^T  (64 batches, M=N=1024, K=64), bf16 store
  g5_gemm<4, 0><<<dim3(16, 8, 64), 256>>>(
      q, k, HDIM, HDIM, HDIM, (size_t)NN * HDIM, (size_t)NN * HDIM, nullptr,
      (float*)s_bf, nullptr, nullptr, NN, (size_t)NN * NN);
  // 3) fused pre-mix + softmax + post-mix -> final attn (reads bf16 s)
  fused_mix_softmax<<<dim3(NN, BB), 256, FUSED_SMEM>>>(wl, bl, ww, bw, s_bf, attn);
  // 4) AV split-K2: halves -> mid / pav1  (64 batches x 2 K-halves)
  g5_gemm<2, 64><<<dim3(1, 8, 128), 256>>>(
      attn, vT, NN, NN, NN, (size_t)NN * NN, (size_t)HDIM * NN, nullptr,
      mid, pav1, nullptr, 0, 0);
  //    reduce: mid += pav1
  red_av<<<(BB * NN * CC) / (256 * 4), 256>>>(mid, pav1);
  // 5) proj split-K2: halves -> out / pp1  (M=4096, N=1024)
  g5_gemm<0, 1><<<dim3(16, 32, 2), 256>>>(
      mid, proj_w, CC, CC, CC, 0, 0, nullptr, out, pp1, nullptr, CC, 0);
  //    reduce: out += pp1 + bias
  red_proj<<<(BB * NN * CC) / (256 * 4), 256>>>(out, pp1, proj_b);
}